// round 8
// baseline (speedup 1.0000x reference)
#include <cuda_runtime.h>
#include <cuda_bf16.h>
#include <math.h>

#define CROP 448
#define NR   56      // cells per side
#define NB   55      // blocks per side
#define B    48
#define IMG  512
#define TOP  32
#define QPR  112     // float4 quads per row (448/4)
#define SGW  456     // padded smem row width: col c at index c+4
#define RPC  2       // cell-rows per CTA in kernel 1
#define NSTG (RPC * 8 + 2)   // 18 staged rows

// Cell histogram scratch: [b][cell_r][cell_c][bin]
__device__ float g_hist[(size_t)B * NR * NR * 9];
// Per-cell sum of squares: [b][cell_r][cell_c]
__device__ float g_cellss[(size_t)B * NR * NR];

__device__ __forceinline__ float fsqrt_approx(float x) {
    float r;
    asm("sqrt.approx.f32 %0, %1;" : "=f"(r) : "f"(x));
    return r;
}

// ---------------------------------------------------------------------------
// Kernel 1: gray -> sqrt -> gradients -> per-cell prefix histograms (+cell ss)
// grid: (NR/RPC, B), block: 448 threads (one per crop column)
// ---------------------------------------------------------------------------
__global__ __launch_bounds__(CROP) void hog_cells_kernel(
    const float* __restrict__ x, const float* __restrict__ coeffs,
    float* __restrict__ hist, float* __restrict__ cellss)
{
    __shared__ float sg[NSTG][SGW];   // rows r0-1 .. r0+16 ; col c at index c+4

    const int crg = blockIdx.x;      // cell-row group 0..27
    const int b   = blockIdx.y;
    const int c   = threadIdx.x;     // crop column 0..447
    const int r0  = crg * (RPC * 8);

    const float c0 = coeffs[0], c1 = coeffs[1], c2 = coeffs[2];
    const float* base = x + (size_t)b * 3 * IMG * IMG;

    // Stage NSTG rows of sqrt(gray); reflection clamp makes boundary gr = 0.
    for (int e = c; e < NSTG * QPR; e += CROP) {
        int i = e / QPR;
        int q = e - i * QPR;
        int r = r0 - 1 + i;
        if (r < 0) r = -r;                        // -1 -> 1
        if (r > CROP - 1) r = 2 * (CROP - 1) - r; // 448 -> 446
        const float4* p = (const float4*)(base + (size_t)(r + TOP) * IMG + TOP) + q;
        float4 a0 = p[0];
        float4 a1 = p[(IMG * IMG) / 4];
        float4 a2 = p[(2 * IMG * IMG) / 4];
        float4 g;
        g.x = fsqrt_approx(fmaf(c0, a0.x, fmaf(c1, a1.x, c2 * a2.x)));
        g.y = fsqrt_approx(fmaf(c0, a0.y, fmaf(c1, a1.y, c2 * a2.y)));
        g.z = fsqrt_approx(fmaf(c0, a0.z, fmaf(c1, a1.z, c2 * a2.z)));
        g.w = fsqrt_approx(fmaf(c0, a0.w, fmaf(c1, a1.w, c2 * a2.w)));
        *((float4*)&sg[i][4 + q * 4]) = g;
    }
    __syncthreads();

    // Reflected edge columns: col -1 -> col 1, col 448 -> col 446.
    if (c < 2 * NSTG) {
        int i = c >> 1;
        if (c & 1) sg[i][452] = sg[i][450];   // col 448 := col 446
        else       sg[i][3]   = sg[i][5];     // col -1  := col 1
    }
    __syncthreads();

    const float SN[8] = {0.342020143f, 0.642787610f, 0.866025404f, 0.984807753f,
                         0.984807753f, 0.866025404f, 0.642787610f, 0.342020143f};
    const float CS[8] = {0.939692621f, 0.766044443f, 0.500000000f, 0.173648178f,
                        -0.173648178f,-0.500000000f,-0.766044443f,-0.939692621f};

    #pragma unroll
    for (int sub = 0; sub < RPC; sub++) {
        // Vertical register pipeline: staged rows 8*sub .. 8*sub+9.
        float vreg[10];
        #pragma unroll
        for (int i = 0; i < 10; i++) vreg[i] = sg[8 * sub + i][c + 4];

        // Prefix histogram: H[k] = sum of mag over pixels with angle >= 20k.
        float H[9];
        #pragma unroll
        for (int k = 0; k < 9; k++) H[k] = 0.f;

        #pragma unroll
        for (int i = 0; i < 8; i++) {
            float gr = vreg[i + 2] - vreg[i];
            float gc = sg[8 * sub + i + 1][c + 5] - sg[8 * sub + i + 1][c + 3];

            float mag = fsqrt_approx(fmaf(gr, gr, gc * gc));

            bool neg = (gr < 0.f) || (gr == 0.f && gc < 0.f);
            float u  = neg ? -gc : gc;
            float vv = neg ? -gr : gr;

            H[0] += mag;
            #pragma unroll
            for (int k = 0; k < 8; k++) {
                float t = fmaf(CS[k], vv, -SN[k] * u);
                if (t >= 0.f) H[k + 1] += mag;
            }
        }

        #pragma unroll
        for (int k = 0; k < 9; k++) {
            H[k] += __shfl_xor_sync(0xffffffffu, H[k], 1);
            H[k] += __shfl_xor_sync(0xffffffffu, H[k], 2);
            H[k] += __shfl_xor_sync(0xffffffffu, H[k], 4);
        }

        if ((c & 7) == 0) {
            int cell = c >> 3;
            int cr = crg * RPC + sub;
            size_t cidx = ((size_t)b * NR + cr) * NR + cell;
            float ss = 0.f;
            #pragma unroll
            for (int k = 0; k < 9; k++) {
                float hk = ((k < 8) ? (H[k] - H[k + 1]) : H[8]) * (1.0f / 64.0f);
                hist[cidx * 9 + k] = hk;
                ss += hk * hk;
            }
            cellss[cidx] = ss;
        }
    }
}

// ---------------------------------------------------------------------------
// Kernel 2: L2-Hys block normalization. One CTA per (b, 5 block-rows).
// grid = B * 11; CTA t handles I = 5t .. 5t+4, staging 6 hist rows once.
// Per row: lane l of warp w handles cell g=l&3 of block J = w + 8*(l>>2);
// all lanes run converged (clamped Jc), store guarded.
// ---------------------------------------------------------------------------
#define K2_THREADS 256
#define IPC 5               // block-rows per CTA
#define NT  11              // CTAs per image (55/5)
#define VSTRIDE 37          // padded per-block stride in vbuf

__global__ __launch_bounds__(K2_THREADS) void hog_blocks_kernel(
    const float* __restrict__ hist, const float* __restrict__ cellss,
    float* __restrict__ out)
{
    __shared__ float sh[(IPC + 1) * NR * 9];   // hist rows I0..I0+5 (3024)
    __shared__ float scs[(IPC + 1) * NR];      // cell ss rows (336)
    __shared__ float vbuf[NB * VSTRIDE];       // normalized blocks, padded

    const int b  = blockIdx.x / NT;
    const int t  = blockIdx.x % NT;
    const int I0 = t * IPC;
    const int tid = threadIdx.x;

    // Stage 6 hist rows as float4 (3024 floats = 756 float4) + cell-ss.
    {
        const float4* src4 = (const float4*)(hist + ((size_t)b * NR + I0) * NR * 9);
        for (int e = tid; e < (IPC + 1) * NR * 9 / 4; e += K2_THREADS)
            ((float4*)sh)[e] = src4[e];
        const float* cs = cellss + ((size_t)b * NR + I0) * NR;
        for (int e = tid; e < (IPC + 1) * NR; e += K2_THREADS)
            scs[e] = cs[e];
    }
    __syncthreads();

    const int w    = tid >> 5;
    const int lane = tid & 31;
    const int g    = lane & 3;            // cell within block
    const int J    = w + 8 * (lane >> 2); // block column (may be >= NB)
    const int Jc   = (J < NB) ? J : (NB - 1);

    // Lane-invariant offsets within a row pair.
    const int cella = (g >> 1) * (NR * 9) + (Jc + (g & 1)) * 9;

    #pragma unroll
    for (int sub = 0; sub < IPC; sub++) {
        const float* shr  = sh  + sub * (NR * 9);
        const float* scsr = scs + sub * NR;

        float inv1 = rsqrtf(scsr[Jc] + scsr[Jc + 1] + scsr[NR + Jc]
                            + scsr[NR + Jc + 1] + 1e-10f);

        const float* cell = shr + cella;
        float v[9];
        float ss = 0.f;
        #pragma unroll
        for (int k = 0; k < 9; k++) {
            float f = fminf(cell[k] * inv1, 0.2f);
            v[k] = f;
            ss = fmaf(f, f, ss);
        }
        ss += __shfl_xor_sync(0xffffffffu, ss, 1);
        ss += __shfl_xor_sync(0xffffffffu, ss, 2);
        float inv2 = rsqrtf(ss + 1e-10f);

        if (J < NB) {
            float* dst = vbuf + J * VSTRIDE + g * 9;
            #pragma unroll
            for (int k = 0; k < 9; k++) dst[k] = v[k] * inv2;
        }
        __syncthreads();

        // Coalesced copy vbuf -> out row I0+sub.
        float* obase = out + ((size_t)b * NB + I0 + sub) * (NB * 36);
        for (int e = tid; e < NB * 36; e += K2_THREADS) {
            int Jx = e / 36;
            int r  = e - Jx * 36;
            obase[e] = vbuf[Jx * VSTRIDE + r];
        }
        __syncthreads();
    }
}

// ---------------------------------------------------------------------------
extern "C" void kernel_launch(void* const* d_in, const int* in_sizes, int n_in,
                              void* d_out, int out_size)
{
    const float* x      = (const float*)d_in[0];
    const float* coeffs = (const float*)d_in[1];
    float* out          = (float*)d_out;

    float *hist, *cellss;
    cudaGetSymbolAddress((void**)&hist, g_hist);
    cudaGetSymbolAddress((void**)&cellss, g_cellss);

    dim3 g1(NR / RPC, B);
    hog_cells_kernel<<<g1, CROP>>>(x, coeffs, hist, cellss);

    hog_blocks_kernel<<<B * NT, K2_THREADS>>>(hist, cellss, out);
}